// round 3
// baseline (speedup 1.0000x reference)
#include <cuda_runtime.h>

// VolumeRenderer: B=4, HW=65536, N=48
// inputs: rgb (B,HW,N,3) f32, sigma (B,HW,N,1) f32, z_vals (B,HW,N) f32
// output: rgb_map (B*HW,3) then depth_map (B*HW), concatenated f32.

#define TOTAL_RAYS (4 * 65536)      // 262144
#define NSAMP      48
#define RAYS_PB    256              // rays (= threads) per block
#define CHUNK      4                // samples per pipeline stage
#define NCHUNKS    (NSAMP / CHUNK)  // 12
#define RP2        257              // float2 pitch (rays + pad)
#define NROWS      10               // 6 rgb-f2 rows + 2 sigma-f2 + 2 z-f2

__device__ __forceinline__ void cp_async8(float2* dst, const float* src) {
    unsigned d = (unsigned)__cvta_generic_to_shared(dst);
    asm volatile("cp.async.ca.shared.global [%0], [%1], 8;" :: "r"(d), "l"(src));
}
__device__ __forceinline__ void cp_commit() {
    asm volatile("cp.async.commit_group;" ::: "memory");
}
template <int N>
__device__ __forceinline__ void cp_wait() {
    asm volatile("cp.async.wait_group %0;" :: "n"(N) : "memory");
}

// Issue the async copies for chunk c of this block into buffer `buf`.
// Transposed layout: rows 0..5 = rgb float2 pairs, 6..7 = sigma, 8..9 = z.
// Source walk is linear over the tile -> coalesced-ish (contiguous per ray row).
__device__ __forceinline__ void prefetch_chunk(
    float2 (*buf)[RP2],
    const float* __restrict__ rgb, const float* __restrict__ sigma,
    const float* __restrict__ z_vals, int ray0, int c, int tid)
{
    // rgb: 12 words = 6 float2 per ray per chunk
#pragma unroll
    for (int i = 0; i < 6; ++i) {
        int f   = tid + RAYS_PB * i;      // 0..1535
        int ray = f / 6;
        int j   = f % 6;                  // float2 index within ray chunk
        const float* src = rgb + (size_t)(ray0 + ray) * (NSAMP * 3)
                               + c * (CHUNK * 3) + 2 * j;
        cp_async8(&buf[j][ray], src);
    }
    // sigma + z: 4 words = 2 float2 per ray per chunk each
#pragma unroll
    for (int i = 0; i < 2; ++i) {
        int f   = tid + RAYS_PB * i;      // 0..511
        int ray = f / 2;
        int j   = f % 2;
        size_t off = (size_t)(ray0 + ray) * NSAMP + c * CHUNK + 2 * j;
        cp_async8(&buf[6 + j][ray], sigma + off);
        cp_async8(&buf[8 + j][ray], z_vals + off);
    }
    cp_commit();
}

__global__ __launch_bounds__(RAYS_PB)
void volrend_kernel(const float* __restrict__ rgb,
                    const float* __restrict__ sigma,
                    const float* __restrict__ z_vals,
                    float* __restrict__ out)
{
    __shared__ float2 buf[2][NROWS][RP2];   // 2 x 10 x 257 x 8B = 41.1 KB

    const int tid   = threadIdx.x;
    const int ray0  = blockIdx.x * RAYS_PB;
    const int ray_g = ray0 + tid;

    // Scan carry. Phantom previous sample (sigma=0) contributes weight 0 and
    // multiplies T by (1+1e-10) once -> negligible vs 1e-3 tolerance.
    float T = 1.0f;
    float acc_r = 0.f, acc_g = 0.f, acc_b = 0.f, acc_d = 0.f;
    float z_p = 0.f, s_p = 0.f, r_p = 0.f, g_p = 0.f, b_p = 0.f;

    prefetch_chunk(buf[0], rgb, sigma, z_vals, ray0, 0, tid);

#pragma unroll
    for (int c = 0; c < NCHUNKS; ++c) {
        // Issue next chunk's copies BEFORE waiting -> they fly during compute.
        if (c + 1 < NCHUNKS) {
            prefetch_chunk(buf[(c + 1) & 1], rgb, sigma, z_vals, ray0, c + 1, tid);
            cp_wait<1>();   // chunk c has landed
        } else {
            cp_wait<0>();
        }
        __syncthreads();    // make every thread's copies visible to all

        const float2 (*bv)[RP2] = buf[c & 1];
        // 2 sample-pairs per chunk; lag-by-one finalization of prior sample.
#pragma unroll
        for (int p = 0; p < 2; ++p) {
            float2 zz = bv[8 + p][tid];
            float2 ss = bv[6 + p][tid];
            float2 c0 = bv[3 * p + 0][tid];   // (r0, g0)
            float2 c1 = bv[3 * p + 1][tid];   // (b0, r1)
            float2 c2 = bv[3 * p + 2][tid];   // (g1, b1)

            // sample 2p
            {
                float dist = zz.x - z_p;
                float e    = __expf(-s_p * dist);
                float w    = T * (1.0f - e);
                acc_r = fmaf(w, r_p, acc_r);
                acc_g = fmaf(w, g_p, acc_g);
                acc_b = fmaf(w, b_p, acc_b);
                acc_d = fmaf(w, z_p, acc_d);
                T *= (e + 1e-10f);
                z_p = zz.x; s_p = ss.x; r_p = c0.x; g_p = c0.y; b_p = c1.x;
            }
            // sample 2p+1
            {
                float dist = zz.y - z_p;
                float e    = __expf(-s_p * dist);
                float w    = T * (1.0f - e);
                acc_r = fmaf(w, r_p, acc_r);
                acc_g = fmaf(w, g_p, acc_g);
                acc_b = fmaf(w, b_p, acc_b);
                acc_d = fmaf(w, z_p, acc_d);
                T *= (e + 1e-10f);
                z_p = zz.y; s_p = ss.y; r_p = c1.y; g_p = c2.x; b_p = c2.y;
            }
        }
        __syncthreads();    // all reads of buf[c&1] done before it is refilled
    }

    // final sample: dist capped at 1e10
    {
        float e = __expf(-s_p * 1e10f);
        float w = T * (1.0f - e);
        acc_r = fmaf(w, r_p, acc_r);
        acc_g = fmaf(w, g_p, acc_g);
        acc_b = fmaf(w, b_p, acc_b);
        acc_d = fmaf(w, z_p, acc_d);
    }

    out[(size_t)ray_g * 3 + 0] = acc_r;
    out[(size_t)ray_g * 3 + 1] = acc_g;
    out[(size_t)ray_g * 3 + 2] = acc_b;
    out[(size_t)TOTAL_RAYS * 3 + ray_g] = acc_d;
}

extern "C" void kernel_launch(void* const* d_in, const int* in_sizes, int n_in,
                              void* d_out, int out_size)
{
    const float* rgb    = (const float*)d_in[0];
    const float* sigma  = (const float*)d_in[1];
    const float* z_vals = (const float*)d_in[2];
    float* out = (float*)d_out;

    dim3 grid(TOTAL_RAYS / RAYS_PB);   // 1024 blocks
    dim3 block(RAYS_PB);               // 256 threads
    volrend_kernel<<<grid, block>>>(rgb, sigma, z_vals, out);
}

// round 4
// speedup vs baseline: 1.3453x; 1.3453x over previous
#include <cuda_runtime.h>

// VolumeRenderer: B=4, HW=65536, N=48
// inputs: rgb (B,HW,N,3) f32, sigma (B,HW,N,1) f32, z_vals (B,HW,N) f32
// output: rgb_map (B*HW,3) then depth_map (B*HW), concatenated f32.

#define TOTAL_RAYS (4 * 65536)      // 262144
#define NSAMP      48
#define RAYS_PB    256              // rays (= threads) per block
#define CHUNK      8                // samples staged per chunk
#define NCHUNKS    (NSAMP / CHUNK)  // 6
#define RP         257              // padded ray pitch in smem

__device__ __forceinline__ void load_chunk(
    float4 rv[6], float4 sv[2], float4 zv[2],
    const float* __restrict__ rgb, const float* __restrict__ sigma,
    const float* __restrict__ z_vals, int ray0, int c, int tid)
{
#pragma unroll
    for (int i = 0; i < 6; ++i) {
        int f = tid + RAYS_PB * i;          // 0..1535 float4s of rgb tile
        int ray = f / 6;                    // 6 float4 = 24 floats per ray
        int j   = f % 6;
        rv[i] = *reinterpret_cast<const float4*>(
            rgb + (size_t)(ray0 + ray) * (NSAMP * 3) + c * (CHUNK * 3) + 4 * j);
    }
#pragma unroll
    for (int i = 0; i < 2; ++i) {
        int f = tid + RAYS_PB * i;          // 0..511 float4s
        int ray = f / 2;                    // 2 float4 = 8 floats per ray
        int j   = f % 2;
        size_t base = (size_t)(ray0 + ray) * NSAMP + c * CHUNK + 4 * j;
        sv[i] = *reinterpret_cast<const float4*>(sigma + base);
        zv[i] = *reinterpret_cast<const float4*>(z_vals + base);
    }
}

__global__ __launch_bounds__(RAYS_PB, 3)
void volrend_kernel(const float* __restrict__ rgb,
                    const float* __restrict__ sigma,
                    const float* __restrict__ z_vals,
                    float* __restrict__ out)
{
    // Transposed staging: [element][ray]. Compute reads are lane==consecutive
    // ray -> conflict-free. Stores <=2-way (RP=257).
    __shared__ float rgb_s[3 * CHUNK][RP];  // 24 rows
    __shared__ float sig_s[CHUNK][RP];
    __shared__ float z_s[CHUNK][RP];

    const int tid   = threadIdx.x;
    const int ray0  = blockIdx.x * RAYS_PB;
    const int ray_g = ray0 + tid;

    // Scan carry. Phantom previous sample (sigma=0) contributes weight 0 and
    // multiplies T by (1+1e-10) once -> negligible vs 1e-3 tolerance.
    float T = 1.0f;
    float acc_r = 0.f, acc_g = 0.f, acc_b = 0.f, acc_d = 0.f;
    float z_p = 0.f, s_p = 0.f, r_p = 0.f, g_p = 0.f, b_p = 0.f;

    float4 rv[6], sv[2], zv[2];
    load_chunk(rv, sv, zv, rgb, sigma, z_vals, ray0, 0, tid);

    for (int c = 0; c < NCHUNKS; ++c) {
        __syncthreads();   // readers of previous chunk done; smem writable

        // ---- transpose-store chunk c from regs into smem
#pragma unroll
        for (int i = 0; i < 6; ++i) {
            int f = tid + RAYS_PB * i;
            int ray = f / 6;
            int e   = 4 * (f % 6);
            rgb_s[e + 0][ray] = rv[i].x;
            rgb_s[e + 1][ray] = rv[i].y;
            rgb_s[e + 2][ray] = rv[i].z;
            rgb_s[e + 3][ray] = rv[i].w;
        }
#pragma unroll
        for (int i = 0; i < 2; ++i) {
            int f = tid + RAYS_PB * i;
            int ray = f / 2;
            int e   = 4 * (f % 2);
            sig_s[e + 0][ray] = sv[i].x;
            sig_s[e + 1][ray] = sv[i].y;
            sig_s[e + 2][ray] = sv[i].z;
            sig_s[e + 3][ray] = sv[i].w;
            z_s[e + 0][ray] = zv[i].x;
            z_s[e + 1][ray] = zv[i].y;
            z_s[e + 2][ray] = zv[i].z;
            z_s[e + 3][ray] = zv[i].w;
        }

        // ---- fire chunk c+1 loads NOW: in flight during barrier + compute
        if (c + 1 < NCHUNKS)
            load_chunk(rv, sv, zv, rgb, sigma, z_vals, ray0, c + 1, tid);

        __syncthreads();

        // ---- per-thread sequential scan over chunk c (lag-by-one)
#pragma unroll
        for (int j = 0; j < CHUNK; ++j) {
            float zc = z_s[j][tid];
            float sc = sig_s[j][tid];
            float rc = rgb_s[3 * j + 0][tid];
            float gc = rgb_s[3 * j + 1][tid];
            float bc = rgb_s[3 * j + 2][tid];

            float dist = zc - z_p;
            float e    = __expf(-s_p * dist);
            float w    = T * (1.0f - e);
            acc_r = fmaf(w, r_p, acc_r);
            acc_g = fmaf(w, g_p, acc_g);
            acc_b = fmaf(w, b_p, acc_b);
            acc_d = fmaf(w, z_p, acc_d);
            T *= (e + 1e-10f);

            z_p = zc; s_p = sc; r_p = rc; g_p = gc; b_p = bc;
        }
    }

    // final sample: dist capped at 1e10
    {
        float e = __expf(-s_p * 1e10f);
        float w = T * (1.0f - e);
        acc_r = fmaf(w, r_p, acc_r);
        acc_g = fmaf(w, g_p, acc_g);
        acc_b = fmaf(w, b_p, acc_b);
        acc_d = fmaf(w, z_p, acc_d);
    }

    out[(size_t)ray_g * 3 + 0] = acc_r;
    out[(size_t)ray_g * 3 + 1] = acc_g;
    out[(size_t)ray_g * 3 + 2] = acc_b;
    out[(size_t)TOTAL_RAYS * 3 + ray_g] = acc_d;
}

extern "C" void kernel_launch(void* const* d_in, const int* in_sizes, int n_in,
                              void* d_out, int out_size)
{
    const float* rgb    = (const float*)d_in[0];
    const float* sigma  = (const float*)d_in[1];
    const float* z_vals = (const float*)d_in[2];
    float* out = (float*)d_out;

    dim3 grid(TOTAL_RAYS / RAYS_PB);   // 1024 blocks
    dim3 block(RAYS_PB);               // 256 threads
    volrend_kernel<<<grid, block>>>(rgb, sigma, z_vals, out);
}

// round 5
// speedup vs baseline: 1.8587x; 1.3816x over previous
#include <cuda_runtime.h>

// VolumeRenderer: B=4, HW=65536, N=48
// inputs: rgb (B,HW,N,3) f32, sigma (B,HW,N,1) f32, z_vals (B,HW,N) f32
// output: rgb_map (B*HW,3) then depth_map (B*HW), concatenated f32.
//
// Decomposition: 16 lanes <-> 16 samples. Each warp = 2 rays, 3 segments of
// 16 samples each. Exclusive cumprod via width-16 multiplicative shuffle
// scan + scalar carry. No shared memory, no barriers, fully coalesced loads.

#define TOTAL_RAYS (4 * 65536)   // 262144
#define NSAMP      48
#define RAYS_PB    16            // 256 threads = 8 warps = 16 rays per block

__global__ __launch_bounds__(256)
void volrend_kernel(const float* __restrict__ rgb,
                    const float* __restrict__ sigma,
                    const float* __restrict__ z_vals,
                    float* __restrict__ out)
{
    const unsigned FULL = 0xffffffffu;
    const int tid  = threadIdx.x;
    const int warp = tid >> 5;
    const int lane = tid & 31;
    const int sub  = lane & 15;          // sample-within-segment
    const int ray  = blockIdx.x * RAYS_PB + warp * 2 + (lane >> 4);

    const size_t zb = (size_t)ray * NSAMP;        // z / sigma base
    const size_t rb = (size_t)ray * (NSAMP * 3);  // rgb base

    // ---- all loads up front: 15 independent LDG.32, fully coalesced ----
    float z0 = z_vals[zb +  0 + sub];
    float z1 = z_vals[zb + 16 + sub];
    float z2 = z_vals[zb + 32 + sub];
    float s0 = sigma [zb +  0 + sub];
    float s1 = sigma [zb + 16 + sub];
    float s2 = sigma [zb + 32 + sub];
    float r0 = rgb[rb + ( 0 + sub) * 3 + 0];
    float g0 = rgb[rb + ( 0 + sub) * 3 + 1];
    float b0 = rgb[rb + ( 0 + sub) * 3 + 2];
    float r1 = rgb[rb + (16 + sub) * 3 + 0];
    float g1 = rgb[rb + (16 + sub) * 3 + 1];
    float b1 = rgb[rb + (16 + sub) * 3 + 2];
    float r2 = rgb[rb + (32 + sub) * 3 + 0];
    float g2 = rgb[rb + (32 + sub) * 3 + 1];
    float b2 = rgb[rb + (32 + sub) * 3 + 2];

    // ---- per-sample distances (z_{i+1} - z_i; last sample capped 1e10) ----
    float z1f = __shfl_sync(FULL, z1, 0, 16);   // first z of seg1 -> whole group
    float z2f = __shfl_sync(FULL, z2, 0, 16);

    float zn0 = __shfl_down_sync(FULL, z0, 1, 16);
    float zn1 = __shfl_down_sync(FULL, z1, 1, 16);
    float zn2 = __shfl_down_sync(FULL, z2, 1, 16);
    float d0 = ((sub == 15) ? z1f : zn0) - z0;
    float d1 = ((sub == 15) ? z2f : zn1) - z1;
    float d2 = (sub == 15) ? 1e10f : (zn2 - z2);

    float carry = 1.0f;                         // product of all t so far
    float pr = 0.f, pg = 0.f, pb = 0.f, pd = 0.f;

#define SEGMENT(ZV, SV, DV, RV, GV, BV)                                   \
    {                                                                     \
        float e = __expf(-(SV) * (DV));                                   \
        float t = e + 1e-10f;                                             \
        float incl = t;                                                   \
        _Pragma("unroll")                                                 \
        for (int k = 1; k < 16; k <<= 1) {                                \
            float v = __shfl_up_sync(FULL, incl, k, 16);                  \
            if (sub >= k) incl *= v;                                      \
        }                                                                 \
        float v1 = __shfl_up_sync(FULL, incl, 1, 16);                     \
        float T  = (sub == 0) ? carry : carry * v1;                       \
        float w  = (1.0f - e) * T;                                        \
        pr = fmaf(w, (RV), pr);                                           \
        pg = fmaf(w, (GV), pg);                                           \
        pb = fmaf(w, (BV), pb);                                           \
        pd = fmaf(w, (ZV), pd);                                           \
        carry *= __shfl_sync(FULL, incl, 15, 16);                         \
    }

    SEGMENT(z0, s0, d0, r0, g0, b0)
    SEGMENT(z1, s1, d1, r1, g1, b1)
    SEGMENT(z2, s2, d2, r2, g2, b2)
#undef SEGMENT

    // ---- reduce the 4 accumulators across the 16-lane group ----
#pragma unroll
    for (int k = 1; k < 16; k <<= 1) {
        pr += __shfl_xor_sync(FULL, pr, k, 16);
        pg += __shfl_xor_sync(FULL, pg, k, 16);
        pb += __shfl_xor_sync(FULL, pb, k, 16);
        pd += __shfl_xor_sync(FULL, pd, k, 16);
    }

    if (sub == 0) {
        out[(size_t)ray * 3 + 0] = pr;
        out[(size_t)ray * 3 + 1] = pg;
        out[(size_t)ray * 3 + 2] = pb;
        out[(size_t)TOTAL_RAYS * 3 + ray] = pd;
    }
}

extern "C" void kernel_launch(void* const* d_in, const int* in_sizes, int n_in,
                              void* d_out, int out_size)
{
    const float* rgb    = (const float*)d_in[0];
    const float* sigma  = (const float*)d_in[1];
    const float* z_vals = (const float*)d_in[2];
    float* out = (float*)d_out;

    dim3 grid(TOTAL_RAYS / RAYS_PB);   // 16384 blocks
    dim3 block(256);
    volrend_kernel<<<grid, block>>>(rgb, sigma, z_vals, out);
}

// round 7
// speedup vs baseline: 1.9396x; 1.0435x over previous
#include <cuda_runtime.h>

// VolumeRenderer: B=4, HW=65536, N=48
// inputs: rgb (B,HW,N,3) f32, sigma (B,HW,N,1) f32, z_vals (B,HW,N) f32
// output: rgb_map (B*HW,3) then depth_map (B*HW), concatenated f32.
//
// Decomposition: 16 lanes <-> 16 samples; warp = 2 rays per "pair".
// Each warp processes TWO ray-pairs, software-pipelined: all loads for
// pair B are issued before pair A's compute, so DRAM traffic stays in
// flight during the shuffle-scan chains. No smem, no barriers.

#define TOTAL_RAYS (4 * 65536)   // 262144
#define NSAMP      48
#define RAYS_PB    32            // 256 threads = 8 warps x 2 pairs x 2 rays

#define FULLM 0xffffffffu

struct RayVals {
    float z0, z1, z2, s0, s1, s2;
    float r0, g0, b0, r1, g1, b1, r2, g2, b2;
};

__device__ __forceinline__ RayVals load_ray(
    const float* __restrict__ rgb, const float* __restrict__ sigma,
    const float* __restrict__ z_vals, int ray, int sub)
{
    const size_t zb = (size_t)ray * NSAMP;
    const size_t rb = (size_t)ray * (NSAMP * 3);
    RayVals v;
    v.z0 = z_vals[zb +  0 + sub];
    v.z1 = z_vals[zb + 16 + sub];
    v.z2 = z_vals[zb + 32 + sub];
    v.s0 = sigma [zb +  0 + sub];
    v.s1 = sigma [zb + 16 + sub];
    v.s2 = sigma [zb + 32 + sub];
    v.r0 = rgb[rb + ( 0 + sub) * 3 + 0];
    v.g0 = rgb[rb + ( 0 + sub) * 3 + 1];
    v.b0 = rgb[rb + ( 0 + sub) * 3 + 2];
    v.r1 = rgb[rb + (16 + sub) * 3 + 0];
    v.g1 = rgb[rb + (16 + sub) * 3 + 1];
    v.b1 = rgb[rb + (16 + sub) * 3 + 2];
    v.r2 = rgb[rb + (32 + sub) * 3 + 0];
    v.g2 = rgb[rb + (32 + sub) * 3 + 1];
    v.b2 = rgb[rb + (32 + sub) * 3 + 2];
    return v;
}

__device__ __forceinline__ void compute_ray(
    const RayVals& v, int ray, int sub, float* __restrict__ out)
{
    // per-sample distances (z_{i+1} - z_i; last capped at 1e10)
    float z1f = __shfl_sync(FULLM, v.z1, 0, 16);
    float z2f = __shfl_sync(FULLM, v.z2, 0, 16);
    float zn0 = __shfl_down_sync(FULLM, v.z0, 1, 16);
    float zn1 = __shfl_down_sync(FULLM, v.z1, 1, 16);
    float zn2 = __shfl_down_sync(FULLM, v.z2, 1, 16);
    float d0 = ((sub == 15) ? z1f : zn0) - v.z0;
    float d1 = ((sub == 15) ? z2f : zn1) - v.z1;
    float d2 = (sub == 15) ? 1e10f : (zn2 - v.z2);

    float carry = 1.0f;
    float pr = 0.f, pg = 0.f, pb = 0.f, pd = 0.f;

#define SEGMENT(ZV, SV, DV, RV, GV, BV)                                   \
    {                                                                     \
        float e = __expf(-(SV) * (DV));                                   \
        float incl = e + 1e-10f;                                          \
        _Pragma("unroll")                                                 \
        for (int k = 1; k < 16; k <<= 1) {                                \
            float u = __shfl_up_sync(FULLM, incl, k, 16);                 \
            if (sub >= k) incl *= u;                                      \
        }                                                                 \
        float v1 = __shfl_up_sync(FULLM, incl, 1, 16);                    \
        float T  = (sub == 0) ? carry : carry * v1;                       \
        float w  = (1.0f - e) * T;                                        \
        pr = fmaf(w, (RV), pr);                                           \
        pg = fmaf(w, (GV), pg);                                           \
        pb = fmaf(w, (BV), pb);                                           \
        pd = fmaf(w, (ZV), pd);                                           \
        carry *= __shfl_sync(FULLM, incl, 15, 16);                        \
    }

    SEGMENT(v.z0, v.s0, d0, v.r0, v.g0, v.b0)
    SEGMENT(v.z1, v.s1, d1, v.r1, v.g1, v.b1)
    SEGMENT(v.z2, v.s2, d2, v.r2, v.g2, v.b2)
#undef SEGMENT

#pragma unroll
    for (int k = 1; k < 16; k <<= 1) {
        pr += __shfl_xor_sync(FULLM, pr, k, 16);
        pg += __shfl_xor_sync(FULLM, pg, k, 16);
        pb += __shfl_xor_sync(FULLM, pb, k, 16);
        pd += __shfl_xor_sync(FULLM, pd, k, 16);
    }

    if (sub == 0) {
        out[(size_t)ray * 3 + 0] = pr;
        out[(size_t)ray * 3 + 1] = pg;
        out[(size_t)ray * 3 + 2] = pb;
        out[(size_t)TOTAL_RAYS * 3 + ray] = pd;
    }
}

__global__ __launch_bounds__(256)
void volrend_kernel(const float* __restrict__ rgb,
                    const float* __restrict__ sigma,
                    const float* __restrict__ z_vals,
                    float* __restrict__ out)
{
    const int tid  = threadIdx.x;
    const int warp = tid >> 5;
    const int lane = tid & 31;
    const int sub  = lane & 15;
    const int half = lane >> 4;

    // warp handles 4 rays: pair A = {base, base+1}, pair B = {base+2, base+3}
    const int base  = blockIdx.x * RAYS_PB + warp * 4;
    const int rayA  = base + half;
    const int rayB  = base + 2 + half;

    // issue ALL loads (A then B) before any compute: B's loads stay in
    // flight across A's entire shuffle-scan chain.
    RayVals va = load_ray(rgb, sigma, z_vals, rayA, sub);
    RayVals vb = load_ray(rgb, sigma, z_vals, rayB, sub);

    compute_ray(va, rayA, sub, out);
    compute_ray(vb, rayB, sub, out);
}

extern "C" void kernel_launch(void* const* d_in, const int* in_sizes, int n_in,
                              void* d_out, int out_size)
{
    const float* rgb    = (const float*)d_in[0];
    const float* sigma  = (const float*)d_in[1];
    const float* z_vals = (const float*)d_in[2];
    float* out = (float*)d_out;

    dim3 grid(TOTAL_RAYS / RAYS_PB);   // 8192 blocks
    dim3 block(256);
    volrend_kernel<<<grid, block>>>(rgb, sigma, z_vals, out);
}